// round 4
// baseline (speedup 1.0000x reference)
#include <cuda_runtime.h>
#include <math.h>

// Problem constants (fixed by reference setup_inputs)
#define BQ      1024
#define DIM     256
#define NTRAIN  200000
#define NCLASS  1000
#define KSEL    20
#define TEMPF   20.0f
#define EPSF    1e-8f

// Tiling
#define BM 128
#define BN 128
#define BKK 32
#define CHUNK   2048
#define NCHUNKS 98        // ceil(200000/2048)
#define QTILES  8         // 1024/128
#define NCAND   (NCHUNKS*KSEL)   // 1960 candidates per query at merge

// Scratch (allocation-free rule: __device__ globals)
__device__ float g_qn[BQ * DIM];
__device__ float g_tinv[NTRAIN];
__device__ float g_pvals[(size_t)BQ * NCHUNKS * KSEL];
__device__ int   g_pidx [(size_t)BQ * NCHUNKS * KSEL];

// ---------------------------------------------------------------------------
// Kernel 1: q = normalize((x - mean) * inv_std)   [one block per query row]
// ---------------------------------------------------------------------------
__global__ void qnorm_kernel(const float* __restrict__ x,
                             const float* __restrict__ mean,
                             const float* __restrict__ inv_std) {
    int b = blockIdx.x;
    int d = threadIdx.x;            // blockDim = 256 = DIM
    float v = (x[b * DIM + d] - mean[d]) * inv_std[d];
    float s = v * v;
    #pragma unroll
    for (int o = 16; o; o >>= 1) s += __shfl_xor_sync(0xffffffffu, s, o);
    __shared__ float ws[8];
    int w = threadIdx.x >> 5, l = threadIdx.x & 31;
    if (l == 0) ws[w] = s;
    __syncthreads();
    if (threadIdx.x == 0) {
        float t = 0.f;
        #pragma unroll
        for (int i = 0; i < 8; i++) t += ws[i];
        ws[0] = t;
    }
    __syncthreads();
    float nrm = sqrtf(ws[0]);
    g_qn[b * DIM + d] = v / fmaxf(nrm, EPSF);
}

// ---------------------------------------------------------------------------
// Kernel 2: per-train-row inverse L2 norm (one warp per row)
// ---------------------------------------------------------------------------
__global__ void tinv_kernel(const float* __restrict__ tx) {
    int gw   = (blockIdx.x * blockDim.x + threadIdx.x) >> 5;
    int lane = threadIdx.x & 31;
    if (gw >= NTRAIN) return;
    const float4* row = (const float4*)(tx + (size_t)gw * DIM);
    float4 a = row[lane * 2];
    float4 b = row[lane * 2 + 1];
    float s = a.x*a.x + a.y*a.y + a.z*a.z + a.w*a.w
            + b.x*b.x + b.y*b.y + b.z*b.z + b.w*b.w;
    #pragma unroll
    for (int o = 16; o; o >>= 1) s += __shfl_xor_sync(0xffffffffu, s, o);
    if (lane == 0) g_tinv[gw] = 1.f / fmaxf(sqrtf(s), EPSF);
}

// ---------------------------------------------------------------------------
// Kernel 3: fused 128x128 fp32 GEMM + per-chunk top-20
//   grid = (NCHUNKS, QTILES), block = 256
// ---------------------------------------------------------------------------
__global__ __launch_bounds__(256)
void knn_main(const float* __restrict__ train) {
    extern __shared__ float sm[];
    float* As   = sm;                         // [32][132]
    float* Bs   = As + 32 * 132;              // [32][132]
    float* sims = Bs + 32 * 132;              // [128][129]
    float* topv = sims + 128 * 129;           // [128] pitch 21
    int*   topi = (int*)(topv + 128 * 21);    // [128] pitch 21
    float* tv   = (float*)(topi + 128 * 21);  // [128]

    const int tid   = threadIdx.x;
    const int qtile = blockIdx.y;
    const int chunk = blockIdx.x;
    const int tbase0 = chunk * CHUNK;
    const int ty = tid >> 4, tx = tid & 15;

    // init top-k lists
    for (int l = tid; l < 128 * KSEL; l += 256)
        topv[(l / KSEL) * 21 + (l % KSEL)] = -INFINITY;
    float minv = -INFINITY; int minp = 0;   // only meaningful for tid<128
    __syncthreads();

    for (int tile = 0; tile < CHUNK / BN; tile++) {
        int tbase = tbase0 + tile * BN;
        if (tbase >= NTRAIN) break;

        float acc[8][8];
        #pragma unroll
        for (int i = 0; i < 8; i++)
            #pragma unroll
            for (int j = 0; j < 8; j++) acc[i][j] = 0.f;

        for (int ks = 0; ks < DIM / BKK; ks++) {
            int kb = ks * BKK;
            // cooperative loads, transposed into smem (pitch 132)
            #pragma unroll
            for (int u = 0; u < 4; u++) {
                int L = tid + u * 256;
                int row = L >> 3, c4 = L & 7;
                float4 va = *(const float4*)(g_qn + (size_t)(qtile * BM + row) * DIM + kb + c4 * 4);
                As[(c4 * 4 + 0) * 132 + row] = va.x;
                As[(c4 * 4 + 1) * 132 + row] = va.y;
                As[(c4 * 4 + 2) * 132 + row] = va.z;
                As[(c4 * 4 + 3) * 132 + row] = va.w;
                int tr = tbase + row;
                float4 vb = make_float4(0.f, 0.f, 0.f, 0.f);
                if (tr < NTRAIN)
                    vb = *(const float4*)(train + (size_t)tr * DIM + kb + c4 * 4);
                Bs[(c4 * 4 + 0) * 132 + row] = vb.x;
                Bs[(c4 * 4 + 1) * 132 + row] = vb.y;
                Bs[(c4 * 4 + 2) * 132 + row] = vb.z;
                Bs[(c4 * 4 + 3) * 132 + row] = vb.w;
            }
            __syncthreads();
            #pragma unroll
            for (int k = 0; k < BKK; k++) {
                float a[8], b[8];
                *(float4*)(a)     = *(const float4*)&As[k * 132 + ty * 8];
                *(float4*)(a + 4) = *(const float4*)&As[k * 132 + ty * 8 + 4];
                *(float4*)(b)     = *(const float4*)&Bs[k * 132 + tx * 8];
                *(float4*)(b + 4) = *(const float4*)&Bs[k * 132 + tx * 8 + 4];
                #pragma unroll
                for (int i = 0; i < 8; i++)
                    #pragma unroll
                    for (int j = 0; j < 8; j++)
                        acc[i][j] += a[i] * b[j];
            }
            __syncthreads();
        }

        // stage sims (pitch 129) + train inv-norm tile
        #pragma unroll
        for (int i = 0; i < 8; i++)
            #pragma unroll
            for (int j = 0; j < 8; j++)
                sims[(ty * 8 + i) * 129 + (tx * 8 + j)] = acc[i][j];
        if (tid >= 128) {
            int j = tid - 128;
            int t = tbase + j;
            tv[j] = (t < NTRAIN) ? g_tinv[t] : 0.f;
        }
        __syncthreads();

        // top-20 update: one thread per query row
        if (tid < 128) {
            const float* srow = sims + tid * 129;
            int lim = min(BN, NTRAIN - tbase);
            float* tvq = topv + tid * 21;
            int*   tiq = topi + tid * 21;
            for (int j = 0; j < lim; j++) {
                float v = srow[j] * tv[j];
                if (v > minv) {
                    tvq[minp] = v;
                    tiq[minp] = tbase + j;
                    minv = tvq[0]; minp = 0;
                    #pragma unroll
                    for (int m = 1; m < KSEL; m++) {
                        float t2 = tvq[m];
                        if (t2 < minv) { minv = t2; minp = m; }
                    }
                }
            }
        }
        __syncthreads();
    }

    if (tid < 128) {
        int q = qtile * BM + tid;
        size_t base = ((size_t)q * NCHUNKS + chunk) * KSEL;
        #pragma unroll
        for (int j = 0; j < KSEL; j++) {
            g_pvals[base + j] = topv[tid * 21 + j];
            g_pidx [base + j] = topi[tid * 21 + j];
        }
    }
}

// ---------------------------------------------------------------------------
// Kernel 4: merge partial top-20s -> global top-20 -> softmax -> scatter
//   grid = BQ, block = 256
// ---------------------------------------------------------------------------
__global__ __launch_bounds__(256)
void knn_merge(const void* __restrict__ ty_raw, float* __restrict__ out) {
    __shared__ float vals[NCAND];
    __shared__ int   idxs[NCAND];
    __shared__ float selv[KSEL];
    __shared__ int   seli[KSEL];
    __shared__ float rv[8];
    __shared__ int   rp[8];

    int q = blockIdx.x, tid = threadIdx.x;
    for (int l = tid; l < NCAND; l += 256) {
        vals[l] = g_pvals[(size_t)q * NCAND + l];
        idxs[l] = g_pidx [(size_t)q * NCAND + l];
    }
    for (int c = tid; c < NCLASS; c += 256) out[(size_t)q * NCLASS + c] = 0.f;
    __syncthreads();

    for (int it = 0; it < KSEL; it++) {
        float bv = -INFINITY; int bp = tid;   // every tid < NCAND, always valid
        for (int l = tid; l < NCAND; l += 256) {
            float v = vals[l];
            if (v > bv) { bv = v; bp = l; }
        }
        #pragma unroll
        for (int o = 16; o; o >>= 1) {
            float ov = __shfl_xor_sync(0xffffffffu, bv, o);
            int   op = __shfl_xor_sync(0xffffffffu, bp, o);
            if (ov > bv || (ov == bv && op < bp)) { bv = ov; bp = op; }
        }
        int w = tid >> 5, l5 = tid & 31;
        if (l5 == 0) { rv[w] = bv; rp[w] = bp; }
        __syncthreads();
        if (tid == 0) {
            float fb = rv[0]; int fp = rp[0];
            #pragma unroll
            for (int i = 1; i < 8; i++)
                if (rv[i] > fb || (rv[i] == fb && rp[i] < fp)) { fb = rv[i]; fp = rp[i]; }
            selv[it] = vals[fp];
            seli[it] = idxs[fp];
            vals[fp] = -INFINITY;
        }
        __syncthreads();
    }

    if (tid == 0) {
        // detect int64 vs int32 labels (deterministic: labels<1000 so int64
        // layout has zero high words at odd int32 positions)
        const int* y32 = (const int*)ty_raw;
        bool is64 = true;
        #pragma unroll
        for (int i = 1; i < 32; i += 2) is64 = is64 && (y32[i] == 0);

        float m0 = selv[0], s = 0.f;
        float w20[KSEL];
        #pragma unroll
        for (int j = 0; j < KSEL; j++) {
            float w = expf((selv[j] - m0) * TEMPF);
            w20[j] = w; s += w;
        }
        float inv = 1.f / s;
        for (int j = 0; j < KSEL; j++) {
            int id  = seli[j];
            int lab = is64 ? (int)((const long long*)ty_raw)[id] : y32[id];
            out[(size_t)q * NCLASS + lab] += w20[j] * inv;
        }
    }
}

// ---------------------------------------------------------------------------
extern "C" void kernel_launch(void* const* d_in, const int* in_sizes, int n_in,
                              void* d_out, int out_size) {
    const float* x       = (const float*)d_in[0];
    const float* mean    = (const float*)d_in[1];
    const float* inv_std = (const float*)d_in[2];
    const float* train_x = (const float*)d_in[3];
    const void*  train_y = d_in[4];
    float* out = (float*)d_out;

    qnorm_kernel<<<BQ, 256>>>(x, mean, inv_std);
    tinv_kernel<<<(NTRAIN + 7) / 8, 256>>>(train_x);

    // dynamic smem: As+Bs (2*32*132) + sims (128*129) + topv/topi (2*128*21) + tv(128)
    size_t smem = (size_t)(2 * 32 * 132 + 128 * 129 + 2 * 128 * 21 + 128) * 4;
    cudaFuncSetAttribute(knn_main, cudaFuncAttributeMaxDynamicSharedMemorySize, (int)smem);
    knn_main<<<dim3(NCHUNKS, QTILES), 256, smem>>>(train_x);

    knn_merge<<<BQ, 256>>>(train_y, out);
}

// round 7
// speedup vs baseline: 3.3946x; 3.3946x over previous
#include <cuda_runtime.h>
#include <cuda_bf16.h>
#include <math.h>
#include <stdint.h>

// Problem constants
#define BQ      1024
#define DIM     256
#define NTRAIN  200000
#define NCLASS  1000
#define KSEL    20
#define KCAND   32          // bf16 candidates kept for fp32 rescoring
#define TEMPF   20.0f
#define EPSF    1e-8f

// Tiling
#define CHUNK    2048
#define NCHUNKS  98
#define NPAD     (NCHUNKS*CHUNK)     // 200704 padded train rows
#define QTILES   8
#define NCANDTOT (NCHUNKS*KSEL)      // 1960 candidates/query
#define TILES_PC 16                  // 128-row tiles per chunk
#define NSLABS   32                  // 2 K-slabs per tile

// knn_main dynamic smem layout (bytes)
#define OFF_A    0u                  // A: 128 rows x 512B (256 bf16)   = 65536
#define OFF_B0   65536u              // B slab: 128 rows x 256B (128 bf16) = 32768
#define OFF_B1   98304u
#define OFF_SIMS 131072u             // 128 x 130 fp32 = 66560
#define OFF_TOPV 197632u             // 128 x 21 fp32  = 10752
#define OFF_TOPI 208384u             // 128 x 21 int   = 10752
#define SMEM_TOT 219136u
#define SIMS_PITCH 130

// Scratch (__device__ globals; no allocations allowed)
__device__ float          g_qn[BQ * DIM];            // fp32 normalized queries
__device__ __nv_bfloat16  g_qb[BQ * DIM];            // bf16 normalized queries
__device__ __nv_bfloat16  g_tb[(size_t)NPAD * DIM];  // bf16 pre-normalized train bank
__device__ float          g_tinv[NPAD];              // 1/max(||t||,eps)
__device__ float g_pvals[(size_t)BQ * NCHUNKS * KSEL];
__device__ int   g_pidx [(size_t)BQ * NCHUNKS * KSEL];

// ---------------------------------------------------------------------------
// Plain-PTX helpers (all valid on base sm_103 target: no "a"-only features)
// ---------------------------------------------------------------------------
__device__ __forceinline__ uint32_t smem_u32(const void* p) {
    uint32_t a;
    asm("{ .reg .u64 t; cvta.to.shared.u64 t, %1; cvt.u32.u64 %0, t; }"
        : "=r"(a) : "l"(p));
    return a;
}
__device__ __forceinline__ void cp16(uint32_t dst, const void* src) {
    asm volatile("cp.async.cg.shared.global [%0], [%1], 16;"
                 :: "r"(dst), "l"(src));
}
#define CP_COMMIT() asm volatile("cp.async.commit_group;" ::: "memory")
#define CP_WAIT1()  asm volatile("cp.async.wait_group 1;" ::: "memory")

__device__ __forceinline__ void ldsm_x4(uint32_t addr, uint32_t& r0, uint32_t& r1,
                                        uint32_t& r2, uint32_t& r3) {
    asm volatile("ldmatrix.sync.aligned.m8n8.x4.shared.b16 {%0,%1,%2,%3}, [%4];"
                 : "=r"(r0), "=r"(r1), "=r"(r2), "=r"(r3) : "r"(addr));
}
__device__ __forceinline__ void mma16816(float* d, const uint32_t* a,
                                         uint32_t b0, uint32_t b1) {
    asm volatile("mma.sync.aligned.m16n8k16.row.col.f32.bf16.bf16.f32 "
                 "{%0,%1,%2,%3}, {%4,%5,%6,%7}, {%8,%9}, {%0,%1,%2,%3};"
                 : "+f"(d[0]), "+f"(d[1]), "+f"(d[2]), "+f"(d[3])
                 : "r"(a[0]), "r"(a[1]), "r"(a[2]), "r"(a[3]), "r"(b0), "r"(b1));
}

// ---------------------------------------------------------------------------
// Kernel 1: q = normalize((x - mean) * inv_std)  -> fp32 + bf16
// ---------------------------------------------------------------------------
__global__ void qnorm_kernel(const float* __restrict__ x,
                             const float* __restrict__ mean,
                             const float* __restrict__ inv_std) {
    int b = blockIdx.x;
    int d = threadIdx.x;            // blockDim = 256 = DIM
    float v = (x[b * DIM + d] - mean[d]) * inv_std[d];
    float s = v * v;
    #pragma unroll
    for (int o = 16; o; o >>= 1) s += __shfl_xor_sync(0xffffffffu, s, o);
    __shared__ float ws[8];
    int w = threadIdx.x >> 5, l = threadIdx.x & 31;
    if (l == 0) ws[w] = s;
    __syncthreads();
    if (threadIdx.x == 0) {
        float t = 0.f;
        #pragma unroll
        for (int i = 0; i < 8; i++) t += ws[i];
        ws[0] = t;
    }
    __syncthreads();
    float outv = v / fmaxf(sqrtf(ws[0]), EPSF);
    g_qn[b * DIM + d] = outv;
    g_qb[b * DIM + d] = __float2bfloat16(outv);
}

// ---------------------------------------------------------------------------
// Kernel 2: bf16 pre-normalized train bank + fp32 inverse norms (one warp/row)
// ---------------------------------------------------------------------------
__global__ void tconv_kernel(const float* __restrict__ tx) {
    int gw   = (blockIdx.x * blockDim.x + threadIdx.x) >> 5;
    int lane = threadIdx.x & 31;
    if (gw >= NPAD) return;
    uint4* dst = (uint4*)(g_tb + (size_t)gw * DIM) + lane;   // 8 bf16 per lane
    if (gw >= NTRAIN) {
        uint4 z; z.x = z.y = z.z = z.w = 0u;
        *dst = z;
        if (lane == 0) g_tinv[gw] = 0.f;
        return;
    }
    const float4* row = (const float4*)(tx + (size_t)gw * DIM);
    float4 a = row[lane * 2];
    float4 b = row[lane * 2 + 1];
    float s = a.x*a.x + a.y*a.y + a.z*a.z + a.w*a.w
            + b.x*b.x + b.y*b.y + b.z*b.z + b.w*b.w;
    #pragma unroll
    for (int o = 16; o; o >>= 1) s += __shfl_xor_sync(0xffffffffu, s, o);
    float inv = 1.f / fmaxf(sqrtf(s), EPSF);
    __nv_bfloat162 p0 = __floats2bfloat162_rn(a.x * inv, a.y * inv);
    __nv_bfloat162 p1 = __floats2bfloat162_rn(a.z * inv, a.w * inv);
    __nv_bfloat162 p2 = __floats2bfloat162_rn(b.x * inv, b.y * inv);
    __nv_bfloat162 p3 = __floats2bfloat162_rn(b.z * inv, b.w * inv);
    uint4 o4;
    o4.x = *(uint32_t*)&p0; o4.y = *(uint32_t*)&p1;
    o4.z = *(uint32_t*)&p2; o4.w = *(uint32_t*)&p3;
    *dst = o4;
    if (lane == 0) g_tinv[gw] = inv;
}

// ---------------------------------------------------------------------------
// B slab loader: 128 rows x 128 bf16 (256B/row, 16 chunks), xor-swizzled
// ---------------------------------------------------------------------------
__device__ __forceinline__ void load_slab(uint32_t smdst,
                                          const __nv_bfloat16* src_base, int tid) {
    #pragma unroll
    for (int k = 0; k < 8; k++) {
        int l = tid + k * 256;
        int row = l >> 4, c = l & 15;
        uint32_t dst = smdst + (uint32_t)row * 256u
                     + (uint32_t)((c ^ (row & 7)) * 16);
        cp16(dst, (const char*)(src_base + (size_t)row * DIM) + c * 16);
    }
}

// ---------------------------------------------------------------------------
// Kernel 3: warp-MMA bf16 GEMM (128x128xK256 per tile) + fused per-chunk top-20
//   grid = (NCHUNKS, QTILES), block = 256 (8 warps, 2M x 4N), 1 CTA/SM
// ---------------------------------------------------------------------------
__global__ __launch_bounds__(256, 1)
void knn_main() {
    extern __shared__ char sm[];
    uint32_t smb = smem_u32(sm);
    const int tid  = threadIdx.x;
    const int wid  = tid >> 5, lane = tid & 31;
    const int wm = wid >> 2, wn = wid & 3;          // warp grid 2 x 4
    const int qtile = blockIdx.y, chunk = blockIdx.x;
    const int tbase0 = chunk * CHUNK;

    float* sims = (float*)(sm + OFF_SIMS);
    float* topv = (float*)(sm + OFF_TOPV);
    int*   topi = (int*)  (sm + OFF_TOPI);

    // init top-k lists
    for (int l = tid; l < 128 * KSEL; l += 256)
        topv[(l / KSEL) * 21 + (l % KSEL)] = -1e30f;

    // Prologue: A tile (queries, 16 chunks/thread) + B slabs 0,1
    {
        const __nv_bfloat16* asrc = g_qb + (size_t)qtile * 128 * DIM;
        #pragma unroll
        for (int k = 0; k < 16; k++) {
            int l = tid + k * 256;
            int row = l >> 5, c = l & 31;
            uint32_t dst = smb + OFF_A + (uint32_t)row * 512u
                         + (uint32_t)((c ^ (row & 7)) * 16);
            cp16(dst, (const char*)(asrc + (size_t)row * DIM) + c * 16);
        }
        load_slab(smb + OFF_B0, g_tb + (size_t)tbase0 * DIM, tid);
        CP_COMMIT();
        load_slab(smb + OFF_B1, g_tb + (size_t)tbase0 * DIM + 128, tid);
        CP_COMMIT();
    }

    // per-thread fragment row bases
    int aRow[4], bRow[2];
    #pragma unroll
    for (int i = 0; i < 4; i++) aRow[i] = wm * 64 + i * 16 + (lane & 15);
    #pragma unroll
    for (int j2 = 0; j2 < 2; j2++)
        bRow[j2] = wn * 32 + j2 * 16 + (lane & 7) + ((lane & 16) >> 1);
    const int aHalf = lane >> 4;         // A: k-half chunk offset
    const int bHalf = (lane >> 3) & 1;   // B: k-half chunk offset

    float minv = -1e30f; int minp = 0;

    for (int t = 0; t < TILES_PC; t++) {
        float acc[4][4][4];
        #pragma unroll
        for (int i = 0; i < 4; i++)
            #pragma unroll
            for (int j = 0; j < 4; j++)
                #pragma unroll
                for (int e = 0; e < 4; e++) acc[i][j][e] = 0.f;

        #pragma unroll
        for (int h = 0; h < 2; h++) {
            CP_WAIT1();
            __syncthreads();           // slab (2t+h) resident in buf[h]
            uint32_t bbase = smb + (h ? OFF_B1 : OFF_B0);
            #pragma unroll
            for (int kk = 0; kk < 8; kk++) {
                uint32_t a[4][4];
                int cA = (h * 8 + kk) * 2 + aHalf;
                #pragma unroll
                for (int i = 0; i < 4; i++) {
                    uint32_t ad = smb + OFF_A + (uint32_t)aRow[i] * 512u
                                + (uint32_t)(((cA ^ (aRow[i] & 7))) * 16);
                    ldsm_x4(ad, a[i][0], a[i][1], a[i][2], a[i][3]);
                }
                uint32_t b[2][4];
                int cB = kk * 2 + bHalf;
                #pragma unroll
                for (int j2 = 0; j2 < 2; j2++) {
                    uint32_t bd = bbase + (uint32_t)bRow[j2] * 256u
                                + (uint32_t)(((cB ^ (bRow[j2] & 7))) * 16);
                    ldsm_x4(bd, b[j2][0], b[j2][1], b[j2][2], b[j2][3]);
                }
                #pragma unroll
                for (int i = 0; i < 4; i++)
                    #pragma unroll
                    for (int j = 0; j < 4; j++)
                        mma16816(acc[i][j], a[i],
                                 b[j >> 1][(j & 1) * 2], b[j >> 1][(j & 1) * 2 + 1]);
            }
            __syncthreads();           // all warps done reading buf[h]
            int s = 2 * t + h;
            if (s + 2 < NSLABS) {
                int tile2 = (s + 2) >> 1, h2 = (s + 2) & 1;
                load_slab(smb + (h2 ? OFF_B1 : OFF_B0),
                          g_tb + (size_t)(tbase0 + tile2 * 128) * DIM + h2 * 128, tid);
            }
            CP_COMMIT();               // always commit to keep group count aligned
        }

        // epilogue: stage sims, then per-query top-20 scan
        #pragma unroll
        for (int i = 0; i < 4; i++) {
            int r0 = wm * 64 + i * 16 + (lane >> 2);
            #pragma unroll
            for (int j = 0; j < 4; j++) {
                int c0 = wn * 32 + j * 8 + 2 * (lane & 3);
                *(float2*)&sims[r0 * SIMS_PITCH + c0] =
                    make_float2(acc[i][j][0], acc[i][j][1]);
                *(float2*)&sims[(r0 + 8) * SIMS_PITCH + c0] =
                    make_float2(acc[i][j][2], acc[i][j][3]);
            }
        }
        __syncthreads();
        if (tid < 128) {
            int tbase = tbase0 + t * 128;
            int lim = min(128, NTRAIN - tbase);
            const float* srow = sims + tid * SIMS_PITCH;
            float* tvq = topv + tid * 21;
            int*   tiq = topi + tid * 21;
            for (int j = 0; j < lim; j++) {
                float v = srow[j];
                if (v > minv) {
                    tvq[minp] = v; tiq[minp] = tbase + j;
                    minv = tvq[0]; minp = 0;
                    #pragma unroll
                    for (int m = 1; m < KSEL; m++) {
                        float t2 = tvq[m];
                        if (t2 < minv) { minv = t2; minp = m; }
                    }
                }
            }
        }
        __syncthreads();
    }

    if (tid < 128) {
        int q = qtile * 128 + tid;
        size_t base = ((size_t)q * NCHUNKS + chunk) * KSEL;
        #pragma unroll
        for (int j = 0; j < KSEL; j++) {
            g_pvals[base + j] = topv[tid * 21 + j];
            g_pidx [base + j] = topi[tid * 21 + j];
        }
    }
}

// ---------------------------------------------------------------------------
// Kernel 4: top-32 bf16 candidates -> fp32 rescore -> top-20 -> softmax/scatter
//   grid = BQ, block = 256
// ---------------------------------------------------------------------------
__global__ __launch_bounds__(256)
void knn_merge(const float* __restrict__ train, const void* __restrict__ ty_raw,
               float* __restrict__ out) {
    __shared__ float vals[NCANDTOT];
    __shared__ int   idxs[NCANDTOT];
    __shared__ __align__(16) float qs[DIM];
    __shared__ int   seli[KCAND];
    __shared__ float rsc[KCAND];
    __shared__ float s2v[KSEL];
    __shared__ int   s2i[KSEL];
    __shared__ float rv[8];
    __shared__ int   rp[8];

    int q = blockIdx.x, tid = threadIdx.x;
    for (int l = tid; l < NCANDTOT; l += 256) {
        vals[l] = g_pvals[(size_t)q * NCANDTOT + l];
        idxs[l] = g_pidx [(size_t)q * NCANDTOT + l];
    }
    qs[tid] = g_qn[(size_t)q * DIM + tid];
    for (int c = tid; c < NCLASS; c += 256) out[(size_t)q * NCLASS + c] = 0.f;
    __syncthreads();

    // select top-KCAND bf16 candidates by iterative block argmax
    for (int it = 0; it < KCAND; it++) {
        float bv = -INFINITY; int bp = tid;
        for (int l = tid; l < NCANDTOT; l += 256) {
            float v = vals[l];
            if (v > bv) { bv = v; bp = l; }
        }
        #pragma unroll
        for (int o = 16; o; o >>= 1) {
            float ov = __shfl_xor_sync(0xffffffffu, bv, o);
            int   op = __shfl_xor_sync(0xffffffffu, bp, o);
            if (ov > bv || (ov == bv && op < bp)) { bv = ov; bp = op; }
        }
        int w = tid >> 5, l5 = tid & 31;
        if (l5 == 0) { rv[w] = bv; rp[w] = bp; }
        __syncthreads();
        if (tid == 0) {
            float fb = rv[0]; int fp = rp[0];
            #pragma unroll
            for (int i = 1; i < 8; i++)
                if (rv[i] > fb || (rv[i] == fb && rp[i] < fp)) { fb = rv[i]; fp = rp[i]; }
            seli[it] = idxs[fp];
            vals[fp] = -INFINITY;
        }
        __syncthreads();
    }

    // exact fp32 rescore: 8 threads per candidate, 32 dims each
    {
        int c = tid >> 3, seg = tid & 7;
        const float4* tr = (const float4*)(train + (size_t)seli[c] * DIM + seg * 32);
        const float4* qq = (const float4*)(qs + seg * 32);
        float s = 0.f;
        #pragma unroll
        for (int i = 0; i < 8; i++) {
            float4 tv = tr[i]; float4 qv = qq[i];
            s += tv.x * qv.x + tv.y * qv.y + tv.z * qv.z + tv.w * qv.w;
        }
        #pragma unroll
        for (int o = 4; o; o >>= 1) s += __shfl_down_sync(0xffffffffu, s, o, 8);
        if (seg == 0) rsc[c] = s * g_tinv[seli[c]];
    }
    __syncthreads();

    // exact top-20 of the 32 rescored candidates (warp 0)
    if (tid < 32) {
        float mv = rsc[tid];
        for (int it = 0; it < KSEL; it++) {
            float bv = mv; int bl = tid;
            #pragma unroll
            for (int o = 16; o; o >>= 1) {
                float ov = __shfl_xor_sync(0xffffffffu, bv, o);
                int   ol = __shfl_xor_sync(0xffffffffu, bl, o);
                if (ov > bv || (ov == bv && ol < bl)) { bv = ov; bl = ol; }
            }
            if (tid == 0) { s2v[it] = bv; s2i[it] = seli[bl]; }
            if (tid == bl) mv = -INFINITY;
        }
        __syncwarp();
    }
    __syncthreads();

    if (tid == 0) {
        // detect int64 vs int32 labels (labels < 1000 -> zero high words)
        const int* y32 = (const int*)ty_raw;
        bool is64 = true;
        #pragma unroll
        for (int i = 1; i < 32; i += 2) is64 = is64 && (y32[i] == 0);

        float m0 = s2v[0], s = 0.f;
        float w20[KSEL];
        #pragma unroll
        for (int j = 0; j < KSEL; j++) {
            float w = expf((s2v[j] - m0) * TEMPF);
            w20[j] = w; s += w;
        }
        float inv = 1.f / s;
        for (int j = 0; j < KSEL; j++) {
            int id  = s2i[j];
            int lab = is64 ? (int)((const long long*)ty_raw)[id] : y32[id];
            out[(size_t)q * NCLASS + lab] += w20[j] * inv;
        }
    }
}

// ---------------------------------------------------------------------------
extern "C" void kernel_launch(void* const* d_in, const int* in_sizes, int n_in,
                              void* d_out, int out_size) {
    const float* x       = (const float*)d_in[0];
    const float* mean    = (const float*)d_in[1];
    const float* inv_std = (const float*)d_in[2];
    const float* train_x = (const float*)d_in[3];
    const void*  train_y = d_in[4];
    float* out = (float*)d_out;

    qnorm_kernel<<<BQ, 256>>>(x, mean, inv_std);
    tconv_kernel<<<NPAD / 8, 256>>>(train_x);          // 1 warp per row

    cudaFuncSetAttribute(knn_main, cudaFuncAttributeMaxDynamicSharedMemorySize, SMEM_TOT);
    knn_main<<<dim3(NCHUNKS, QTILES), 256, SMEM_TOT>>>();

    knn_merge<<<BQ, 256>>>(train_x, train_y, out);
}